// round 10
// baseline (speedup 1.0000x reference)
#include <cuda_runtime.h>
#include <cuda_fp16.h>
#include <cstdint>
#include <math.h>

#define NROWS 8192
#define DIM   128
#define HID1  512
#define HID2  256
#define NUSERS 512

#define ROWB   144
#define CHUNKB (64 * ROWB)      // one 64-col k-chunk of a 64-row activation tile: 9216 B
#define WSTGB  (128 * ROWB)     // one W k-chunk (128 n-rows): 18432 B

// dynamic smem layout
#define OFF_W   0                         // 2 x WSTGB   (W double buffer)
#define OFF_A0  (2 * WSTGB)               // 2 chunks    (a0 tile, K=128)
#define OFF_A1  (OFF_A0 + 2 * CHUNKB)     // 8 chunks    (a1 tile, K=512)
#define OFF_A2  (OFF_A1 + 8 * CHUNKB)     // 4 chunks    (a2 tile, K=256)
#define OFF_SQP (OFF_A2 + 4 * CHUNKB)     // 256 floats  (norm reduce)
#define SMEM_TOTAL (OFF_SQP + 1024)       // 166912

// ============ scratch ============
__device__ __align__(256) __half g_a0[NROWS * DIM];     // [8192, 128]
__device__ __align__(256) __half g_w1[HID1 * DIM];      // [512, 128]  (W1^T)
__device__ __align__(256) __half g_w2[HID2 * HID1];     // [256, 512]  (W2^T)
__device__ __align__(256) __half g_w3[DIM * HID2];      // [128, 256]  (W3^T)
__device__ int g_cnt[NUSERS], g_off[NUSERS];
__device__ int g_idx[NROWS], g_tsb[NROWS];
__device__ int g_rowcnt[NROWS];
__device__ int g_is64, g_clickbyte;

// ============================ helpers ============================
__device__ __forceinline__ uint32_t smem_to_u32(const void* p) {
    uint32_t a;
    asm("{ .reg .u64 t; cvta.to.shared.u64 t, %1; cvt.u32.u64 %0, t; }" : "=r"(a) : "l"(p));
    return a;
}
__device__ __forceinline__ void cp_async16(uint32_t smem, const void* gmem) {
    asm volatile("cp.async.cg.shared.global [%0], [%1], 16;" :: "r"(smem), "l"(gmem));
}
#define CP_COMMIT() asm volatile("cp.async.commit_group;" ::: "memory")
#define CP_WAIT(n)  asm volatile("cp.async.wait_group %0;" :: "n"(n) : "memory")

__device__ __forceinline__ void ldsm_x4(uint32_t r[4], uint32_t addr) {
    asm volatile("ldmatrix.sync.aligned.m8n8.x4.shared.b16 {%0,%1,%2,%3}, [%4];"
                 : "=r"(r[0]), "=r"(r[1]), "=r"(r[2]), "=r"(r[3]) : "r"(addr));
}
__device__ __forceinline__ void mma_fp16(float d[4], const uint32_t a[4], const uint32_t b[2]) {
    asm volatile(
        "mma.sync.aligned.m16n8k16.row.col.f32.f16.f16.f32 "
        "{%0,%1,%2,%3}, {%4,%5,%6,%7}, {%8,%9}, {%0,%1,%2,%3};"
        : "+f"(d[0]), "+f"(d[1]), "+f"(d[2]), "+f"(d[3])
        : "r"(a[0]), "r"(a[1]), "r"(a[2]), "r"(a[3]), "r"(b[0]), "r"(b[1]));
}
__device__ __forceinline__ int ld_user(const void* p, int j, int is64) {
    return is64 ? (int)((const long long*)p)[j] : ((const int*)p)[j];
}
__device__ __forceinline__ long long ld_ts(const void* p, int j, int is64) {
    return is64 ? ((const long long*)p)[j] : (long long)((const int*)p)[j];
}
__device__ __forceinline__ int ld_click(const void* p, int j, int cb) {
    return cb ? (((const unsigned char*)p)[j] != 0) : (((const int*)p)[j] != 0);
}

// ============ fused prep: detect + count + scan + scatter + sort (1 block) ============
__global__ void k_prep(const void* __restrict__ user, const void* __restrict__ ts,
                       const void* __restrict__ click) {
    __shared__ int cnt[NUSERS], off[NUSERS], fill[NUSERS];
    __shared__ int s_ts_or, s_click_big;
    int t = threadIdx.x;
    if (t == 0) { s_ts_or = 0; s_click_big = 0; }
    __syncthreads();
    {
        const unsigned int* tsw = (const unsigned int*)ts;
        unsigned int acc = 0;
        for (int i = t; i < 2048; i += NUSERS) acc |= tsw[2 * i + 1];
        if (acc) atomicOr(&s_ts_or, 1);
        const unsigned int* cw = (const unsigned int*)click;
        int big = 0;
        for (int i = t; i < 2048; i += NUSERS) if (cw[i] > 1u) big = 1;
        if (big) atomicOr(&s_click_big, 1);
    }
    cnt[t] = 0; fill[t] = 0;
    __syncthreads();
    int is64 = (s_ts_or == 0) ? 1 : 0;
    int cb = s_click_big ? 1 : 0;
    for (int j = t; j < NROWS; j += NUSERS)
        if (ld_click(click, j, cb)) atomicAdd(&cnt[ld_user(user, j, is64)], 1);
    __syncthreads();
    {
        int v = cnt[t];
        off[t] = v;
        __syncthreads();
        for (int o = 1; o < NUSERS; o <<= 1) {
            int x = (t >= o) ? off[t - o] : 0;
            __syncthreads();
            off[t] += x;
            __syncthreads();
        }
        off[t] -= v;
    }
    __syncthreads();
    for (int j = t; j < NROWS; j += NUSERS)
        if (ld_click(click, j, cb)) {
            int u = ld_user(user, j, is64);
            int pos = off[u] + atomicAdd(&fill[u], 1);
            g_idx[pos] = j;
            g_tsb[pos] = (int)ld_ts(ts, j, is64);
        }
    __syncthreads();
    {
        int b = off[t], n = cnt[t];
        for (int i = 1; i < n; i++) {
            int kj = g_idx[b + i], kt = g_tsb[b + i];
            int p = i - 1;
            while (p >= 0 && g_idx[b + p] > kj) {
                g_idx[b + p + 1] = g_idx[b + p];
                g_tsb[b + p + 1] = g_tsb[b + p];
                p--;
            }
            g_idx[b + p + 1] = kj;
            g_tsb[b + p + 1] = kt;
        }
    }
    g_off[t] = off[t];
    g_cnt[t] = cnt[t];
    if (t == 0) { g_is64 = is64; g_clickbyte = cb; }
}

// ============ history: mean of clicked-earlier ad rows -> fp16 ============
__global__ void k_hist(const float* __restrict__ ad, const void* __restrict__ user,
                       const void* __restrict__ ts) {
    int i = blockIdx.x;
    int t = threadIdx.x;           // 0..127 dim
    int is64 = g_is64;
    int u = ld_user(user, i, is64);
    long long ti = ld_ts(ts, i, is64);
    int b = g_off[u], n = g_cnt[u];
    float acc = 0.f;
    int c = 0;
    for (int k = 0; k < n; k++) {
        if ((long long)g_tsb[b + k] < ti) {
            acc += ad[g_idx[b + k] * DIM + t];
            c++;
        }
    }
    float v = c ? acc / (float)c : 0.f;
    g_a0[i * DIM + t] = __float2half(v);
    if (t == 0) g_rowcnt[i] = c;
}

// ============ weight transpose -> fp16 ============
__global__ void k_wt(const float* __restrict__ W1, const float* __restrict__ W2,
                     const float* __restrict__ W3) {
    int stride = gridDim.x * blockDim.x;
    int tid = blockIdx.x * blockDim.x + threadIdx.x;
    for (int i = tid; i < DIM * HID1; i += stride) {       // W1 [128,512] -> g_w1 [512,128]
        int k = i >> 9, n = i & 511;
        g_w1[n * DIM + k] = __float2half(W1[i]);
    }
    for (int i = tid; i < HID1 * HID2; i += stride) {      // W2 [512,256] -> g_w2 [256,512]
        int k = i >> 8, n = i & 255;
        g_w2[n * HID1 + k] = __float2half(W2[i]);
    }
    for (int i = tid; i < HID2 * DIM; i += stride) {       // W3 [256,128] -> g_w3 [128,256]
        int k = i >> 7, n = i & 127;
        g_w3[n * HID2 + k] = __float2half(W3[i]);
    }
}

// ============ one fused-MLP pass: 64x128 output tile over NCH k-chunks ============
// A read from SMEM chunk array at aBase. W streamed from global via double buffer.
// PHASE 0: bias+SiLU -> fp16 into SMEM activation region (chunk layout, cols bnW..bnW+127).
// PHASE 1: bias -> L2 norm -> empty mask -> fp32 global out (cols 0..127).
template<int NCH, int PHASE>
__device__ __forceinline__ void mlp_pass(
    char* sm, uint32_t smem0,
    const __half* __restrict__ Wg, int Kw, int bnW,
    uint32_t aBase, const float* __restrict__ bias,
    uint32_t outBase,
    const int* __restrict__ rowcnt, float* __restrict__ outF, int bm)
{
    const int tid = threadIdx.x, wid = tid >> 5, lane = tid & 31;
    const int wm = wid & 1, wn = wid >> 1;            // 2 (m) x 4 (n) warps
    const int lq = lane & 3, lr = lane >> 2;
    const uint32_t aOff = (uint32_t)((((lane >> 3) & 1) * 8 + (lane & 7)) * ROWB
                                     + (lane >> 4) * 16 + (wm * 32) * ROWB);
    const uint32_t bOff = (uint32_t)(((((lane >> 4) & 1) * 8) + (lane & 7)) * ROWB
                                     + ((lane >> 3) & 1) * 16 + (wn * 32) * ROWB);

    float d[2][4][4];
    #pragma unroll
    for (int mt = 0; mt < 2; mt++)
        #pragma unroll
        for (int nt = 0; nt < 4; nt++)
            #pragma unroll
            for (int q = 0; q < 4; q++) d[mt][nt][q] = 0.f;

    auto load_w = [&](int s, int ch) {
        uint32_t sb = smem0 + (uint32_t)(OFF_W + s * WSTGB);
        #pragma unroll
        for (int i = tid; i < 1024; i += 256) {
            int r = i >> 3, c = i & 7;
            cp_async16(sb + (uint32_t)(r * ROWB + c * 16),
                       Wg + (size_t)(bnW + r) * Kw + ch * 64 + c * 8);
        }
    };

    load_w(0, 0);
    CP_COMMIT();
    for (int ch = 0; ch < NCH; ch++) {
        if (ch + 1 < NCH) { load_w((ch + 1) & 1, ch + 1); CP_COMMIT(); CP_WAIT(1); }
        else              { CP_WAIT(0); }
        __syncthreads();
        uint32_t sA = aBase + (uint32_t)ch * CHUNKB;
        uint32_t sB = smem0 + (uint32_t)(OFF_W + (ch & 1) * WSTGB);
        #pragma unroll
        for (int ks = 0; ks < 4; ks++) {
            uint32_t Af[2][4], Bf[2][4];
            ldsm_x4(Af[0], sA + aOff + (uint32_t)(ks * 32));
            ldsm_x4(Af[1], sA + aOff + (uint32_t)(16 * ROWB + ks * 32));
            ldsm_x4(Bf[0], sB + bOff + (uint32_t)(ks * 32));
            ldsm_x4(Bf[1], sB + bOff + (uint32_t)(16 * ROWB + ks * 32));
            #pragma unroll
            for (int mt = 0; mt < 2; mt++)
                #pragma unroll
                for (int nt = 0; nt < 4; nt++)
                    mma_fp16(d[mt][nt], Af[mt], &Bf[nt >> 1][(nt & 1) * 2]);
        }
        __syncthreads();
    }

    if (PHASE == 0) {
        // bias + SiLU -> fp16 SMEM store (chunk layout)
        #pragma unroll
        for (int mt = 0; mt < 2; mt++) {
            #pragma unroll
            for (int nt = 0; nt < 4; nt++) {
                int col = wn * 32 + nt * 8 + lq * 2;
                int gcol = bnW + col;
                float2 bb = *(const float2*)&bias[gcol];
                #pragma unroll
                for (int h = 0; h < 2; h++) {
                    int row = wm * 32 + mt * 16 + lr + h * 8;
                    float x0 = d[mt][nt][2 * h + 0] + bb.x;
                    float x1 = d[mt][nt][2 * h + 1] + bb.y;
                    float s0 = x0 / (1.f + __expf(-x0));
                    float s1 = x1 / (1.f + __expf(-x1));
                    __half2 p = __floats2half2_rn(s0, s1);
                    uint32_t addr = outBase + (uint32_t)((gcol >> 6) * CHUNKB
                                                        + row * ROWB + (gcol & 63) * 2);
                    asm volatile("st.shared.u32 [%0], %1;" :: "r"(addr), "r"(*(uint32_t*)&p));
                }
            }
        }
        // next pass's wait+sync orders these writes before any SMEM A reads
    } else {
        // bias + L2 norm + empty mask; deterministic reduce over n-warps
        float* sqp = (float*)(sm + OFF_SQP);   // [4 n-warps][64 rows]
        if (tid < 256) sqp[tid] = 0.f;
        __syncthreads();
        #pragma unroll
        for (int mt = 0; mt < 2; mt++) {
            #pragma unroll
            for (int h = 0; h < 2; h++) {
                float s = 0.f;
                #pragma unroll
                for (int nt = 0; nt < 4; nt++) {
                    int col = wn * 32 + nt * 8 + lq * 2;
                    float2 bb = *(const float2*)&bias[col];
                    float e0 = d[mt][nt][2 * h + 0] + bb.x;
                    float e1 = d[mt][nt][2 * h + 1] + bb.y;
                    s += e0 * e0 + e1 * e1;
                }
                s += __shfl_xor_sync(0xffffffffu, s, 1);
                s += __shfl_xor_sync(0xffffffffu, s, 2);
                if (lq == 0) sqp[wn * 64 + wm * 32 + mt * 16 + lr + h * 8] = s;
            }
        }
        __syncthreads();
        #pragma unroll
        for (int mt = 0; mt < 2; mt++) {
            #pragma unroll
            for (int h = 0; h < 2; h++) {
                int rl = wm * 32 + mt * 16 + lr + h * 8;
                float S = sqp[rl] + sqp[64 + rl] + sqp[128 + rl] + sqp[192 + rl];
                float sc = 0.f;
                if (rowcnt[bm + rl] > 0 && S > 0.f) sc = rsqrtf(S);
                #pragma unroll
                for (int nt = 0; nt < 4; nt++) {
                    int col = wn * 32 + nt * 8 + lq * 2;
                    float2 bb = *(const float2*)&bias[col];
                    float2 v;
                    v.x = (d[mt][nt][2 * h + 0] + bb.x) * sc;
                    v.y = (d[mt][nt][2 * h + 1] + bb.y) * sc;
                    *(float2*)&outF[(size_t)(bm + rl) * 128 + col] = v;
                }
            }
        }
    }
}

// ============ fused MLP: one CTA owns a 64-row stripe through all 3 layers ============
__global__ __launch_bounds__(256)
void k_mlp(const __half* __restrict__ a0g,
           const __half* __restrict__ w1, const __half* __restrict__ w2,
           const __half* __restrict__ w3,
           const float* __restrict__ b1, const float* __restrict__ b2,
           const float* __restrict__ b3,
           const int* __restrict__ rowcnt, float* __restrict__ out)
{
    extern __shared__ char sm[];
    uint32_t smem0 = smem_to_u32(sm);
    const int tid = threadIdx.x;
    const int bm = blockIdx.x * 64;
    uint32_t A0 = smem0 + OFF_A0, A1 = smem0 + OFF_A1, A2 = smem0 + OFF_A2;

    // prologue: a0 tile (2 k-chunks); joins pass0's first commit group
    for (int i = tid; i < 1024; i += 256) {
        int ck = i >> 9, rem = i & 511, r = rem >> 3, c = rem & 7;
        cp_async16(A0 + (uint32_t)(ck * CHUNKB + r * ROWB + c * 16),
                   a0g + (size_t)(bm + r) * 128 + ck * 64 + c * 8);
    }

    // L1: 4 N-chunks of 128 cols, K=128 (2 chunks)
    mlp_pass<2, 0>(sm, smem0, w1, 128, 0,   A0, b1, A1, nullptr, nullptr, bm);
    mlp_pass<2, 0>(sm, smem0, w1, 128, 128, A0, b1, A1, nullptr, nullptr, bm);
    mlp_pass<2, 0>(sm, smem0, w1, 128, 256, A0, b1, A1, nullptr, nullptr, bm);
    mlp_pass<2, 0>(sm, smem0, w1, 128, 384, A0, b1, A1, nullptr, nullptr, bm);
    // L2: 2 N-chunks of 128 cols, K=512 (8 chunks)
    mlp_pass<8, 0>(sm, smem0, w2, 512, 0,   A1, b2, A2, nullptr, nullptr, bm);
    mlp_pass<8, 0>(sm, smem0, w2, 512, 128, A1, b2, A2, nullptr, nullptr, bm);
    // L3: K=256 (4 chunks) -> bias + L2norm + mask -> out
    mlp_pass<4, 1>(sm, smem0, w3, 256, 0,   A2, b3, 0,  rowcnt, out, bm);
}

// ============================ launch ============================
extern "C" void kernel_launch(void* const* d_in, const int* in_sizes, int n_in,
                              void* d_out, int out_size) {
    const float* ad    = (const float*)d_in[0];
    const void*  user  = d_in[1];
    const void*  ts    = d_in[2];
    const void*  click = d_in[3];
    const float* W1 = (const float*)d_in[4];
    const float* b1 = (const float*)d_in[5];
    const float* W2 = (const float*)d_in[6];
    const float* b2 = (const float*)d_in[7];
    const float* W3 = (const float*)d_in[8];
    const float* b3 = (const float*)d_in[9];
    float* out = (float*)d_out;

    cudaFuncSetAttribute(k_mlp, cudaFuncAttributeMaxDynamicSharedMemorySize, SMEM_TOTAL);

    __half *a0, *w1, *w2, *w3;
    int* rowcnt;
    cudaGetSymbolAddress((void**)&a0, g_a0);
    cudaGetSymbolAddress((void**)&w1, g_w1);
    cudaGetSymbolAddress((void**)&w2, g_w2);
    cudaGetSymbolAddress((void**)&w3, g_w3);
    cudaGetSymbolAddress((void**)&rowcnt, g_rowcnt);

    k_prep<<<1, NUSERS>>>(user, ts, click);
    k_wt<<<128, 256>>>(W1, W2, W3);
    k_hist<<<NROWS, DIM>>>(ad, user, ts);

    k_mlp<<<NROWS / 64, 256, SMEM_TOTAL>>>(a0, w1, w2, w3, b1, b2, b3, rowcnt, out);
}

// round 11
// speedup vs baseline: 1.0835x; 1.0835x over previous
#include <cuda_runtime.h>
#include <cuda_fp16.h>
#include <cstdint>
#include <math.h>

#define NROWS 8192
#define DIM   128
#define HID1  512
#define HID2  256
#define NUSERS 512

#define ROWB   144
#define CH32   (32 * ROWB)      // one 64-col k-chunk of a 32-row activation tile: 4608 B
#define WSTGB  (128 * ROWB)     // one W k-chunk (128 n-rows): 18432 B

// dynamic smem layout (per CTA: 101888 B -> 2 CTAs/SM)
#define OFF_W   0                         // 2 x WSTGB = 36864
#define OFF_A0  (2 * WSTGB)               // 2 chunks  =  9216
#define OFF_A1  (OFF_A0 + 2 * CH32)       // 8 chunks  = 36864
#define OFF_A2  (OFF_A1 + 8 * CH32)       // 4 chunks  = 18432
#define OFF_SQP (OFF_A2 + 4 * CH32)       // 128 floats
#define SMEM_TOTAL (OFF_SQP + 512)        // 101888

// ============ scratch ============
__device__ __align__(256) __half g_a0[NROWS * DIM];     // [8192, 128]
__device__ __align__(256) __half g_w1[HID1 * DIM];      // [512, 128]  (W1^T)
__device__ __align__(256) __half g_w2[HID2 * HID1];     // [256, 512]  (W2^T)
__device__ __align__(256) __half g_w3[DIM * HID2];      // [128, 256]  (W3^T)
__device__ int g_cnt[NUSERS], g_off[NUSERS];
__device__ int g_idx[NROWS], g_tsb[NROWS];
__device__ int g_rowcnt[NROWS];
__device__ int g_is64, g_clickbyte;

// ============================ helpers ============================
__device__ __forceinline__ uint32_t smem_to_u32(const void* p) {
    uint32_t a;
    asm("{ .reg .u64 t; cvta.to.shared.u64 t, %1; cvt.u32.u64 %0, t; }" : "=r"(a) : "l"(p));
    return a;
}
__device__ __forceinline__ void cp_async16(uint32_t smem, const void* gmem) {
    asm volatile("cp.async.cg.shared.global [%0], [%1], 16;" :: "r"(smem), "l"(gmem));
}
#define CP_COMMIT() asm volatile("cp.async.commit_group;" ::: "memory")
#define CP_WAIT(n)  asm volatile("cp.async.wait_group %0;" :: "n"(n) : "memory")

__device__ __forceinline__ void ldsm_x4(uint32_t r[4], uint32_t addr) {
    asm volatile("ldmatrix.sync.aligned.m8n8.x4.shared.b16 {%0,%1,%2,%3}, [%4];"
                 : "=r"(r[0]), "=r"(r[1]), "=r"(r[2]), "=r"(r[3]) : "r"(addr));
}
__device__ __forceinline__ void mma_fp16(float d[4], const uint32_t a[4], const uint32_t b[2]) {
    asm volatile(
        "mma.sync.aligned.m16n8k16.row.col.f32.f16.f16.f32 "
        "{%0,%1,%2,%3}, {%4,%5,%6,%7}, {%8,%9}, {%0,%1,%2,%3};"
        : "+f"(d[0]), "+f"(d[1]), "+f"(d[2]), "+f"(d[3])
        : "r"(a[0]), "r"(a[1]), "r"(a[2]), "r"(a[3]), "r"(b[0]), "r"(b[1]));
}
__device__ __forceinline__ int ld_user(const void* p, int j, int is64) {
    return is64 ? (int)((const long long*)p)[j] : ((const int*)p)[j];
}
__device__ __forceinline__ long long ld_ts(const void* p, int j, int is64) {
    return is64 ? ((const long long*)p)[j] : (long long)((const int*)p)[j];
}
__device__ __forceinline__ int ld_click(const void* p, int j, int cb) {
    return cb ? (((const unsigned char*)p)[j] != 0) : (((const int*)p)[j] != 0);
}

// ============ merged prep (block 0) + weight transpose (blocks 1..128) ============
__global__ void k_prep_wt(const void* __restrict__ user, const void* __restrict__ ts,
                          const void* __restrict__ click,
                          const float* __restrict__ W1, const float* __restrict__ W2,
                          const float* __restrict__ W3) {
    if (blockIdx.x == 0) {
        __shared__ int cnt[NUSERS], off[NUSERS], fill[NUSERS];
        __shared__ int s_ts_or, s_click_big;
        int t = threadIdx.x;
        if (t == 0) { s_ts_or = 0; s_click_big = 0; }
        __syncthreads();
        {
            const unsigned int* tsw = (const unsigned int*)ts;
            unsigned int acc = 0;
            for (int i = t; i < 2048; i += NUSERS) acc |= tsw[2 * i + 1];
            if (acc) atomicOr(&s_ts_or, 1);
            const unsigned int* cw = (const unsigned int*)click;
            int big = 0;
            for (int i = t; i < 2048; i += NUSERS) if (cw[i] > 1u) big = 1;
            if (big) atomicOr(&s_click_big, 1);
        }
        cnt[t] = 0; fill[t] = 0;
        __syncthreads();
        int is64 = (s_ts_or == 0) ? 1 : 0;
        int cb = s_click_big ? 1 : 0;
        for (int j = t; j < NROWS; j += NUSERS)
            if (ld_click(click, j, cb)) atomicAdd(&cnt[ld_user(user, j, is64)], 1);
        __syncthreads();
        {
            int v = cnt[t];
            off[t] = v;
            __syncthreads();
            for (int o = 1; o < NUSERS; o <<= 1) {
                int x = (t >= o) ? off[t - o] : 0;
                __syncthreads();
                off[t] += x;
                __syncthreads();
            }
            off[t] -= v;
        }
        __syncthreads();
        for (int j = t; j < NROWS; j += NUSERS)
            if (ld_click(click, j, cb)) {
                int u = ld_user(user, j, is64);
                int pos = off[u] + atomicAdd(&fill[u], 1);
                g_idx[pos] = j;
                g_tsb[pos] = (int)ld_ts(ts, j, is64);
            }
        __syncthreads();
        {
            int b = off[t], n = cnt[t];
            for (int i = 1; i < n; i++) {
                int kj = g_idx[b + i], kt = g_tsb[b + i];
                int p = i - 1;
                while (p >= 0 && g_idx[b + p] > kj) {
                    g_idx[b + p + 1] = g_idx[b + p];
                    g_tsb[b + p + 1] = g_tsb[b + p];
                    p--;
                }
                g_idx[b + p + 1] = kj;
                g_tsb[b + p + 1] = kt;
            }
        }
        g_off[t] = off[t];
        g_cnt[t] = cnt[t];
        if (t == 0) { g_is64 = is64; g_clickbyte = cb; }
    } else {
        int stride = 128 * 512;
        int tid = (blockIdx.x - 1) * 512 + threadIdx.x;
        for (int i = tid; i < DIM * HID1; i += stride) {       // W1 [128,512] -> g_w1 [512,128]
            int k = i >> 9, n = i & 511;
            g_w1[n * DIM + k] = __float2half(W1[i]);
        }
        for (int i = tid; i < HID1 * HID2; i += stride) {      // W2 [512,256] -> g_w2 [256,512]
            int k = i >> 8, n = i & 255;
            g_w2[n * HID1 + k] = __float2half(W2[i]);
        }
        for (int i = tid; i < HID2 * DIM; i += stride) {       // W3 [256,128] -> g_w3 [128,256]
            int k = i >> 7, n = i & 127;
            g_w3[n * HID2 + k] = __float2half(W3[i]);
        }
    }
}

// ============ history: mean of clicked-earlier ad rows -> fp16 ============
__global__ void k_hist(const float* __restrict__ ad, const void* __restrict__ user,
                       const void* __restrict__ ts) {
    int i = blockIdx.x;
    int t = threadIdx.x;           // 0..127 dim
    int is64 = g_is64;
    int u = ld_user(user, i, is64);
    long long ti = ld_ts(ts, i, is64);
    int b = g_off[u], n = g_cnt[u];
    float acc = 0.f;
    int c = 0;
    for (int k = 0; k < n; k++) {
        if ((long long)g_tsb[b + k] < ti) {
            acc += ad[g_idx[b + k] * DIM + t];
            c++;
        }
    }
    float v = c ? acc / (float)c : 0.f;
    g_a0[i * DIM + t] = __float2half(v);
    if (t == 0) g_rowcnt[i] = c;
}

// ============ fused-MLP pass: 32x128 output tile over NCH k-chunks ============
// A from SMEM chunk array at aBase (32-row chunks). W streamed global -> smem db.
// PHASE 0: bias+SiLU -> fp16 into SMEM chunk layout at outBase (cols bnW..bnW+127).
// PHASE 1: bias -> L2 norm -> empty mask -> fp32 global out (cols 0..127).
template<int NCH, int PHASE>
__device__ __forceinline__ void mlp_pass(
    char* sm, uint32_t smem0,
    const __half* __restrict__ Wg, int Kw, int bnW,
    uint32_t aBase, const float* __restrict__ bias,
    uint32_t outBase,
    const int* __restrict__ rowcnt, float* __restrict__ outF, int bm)
{
    const int tid = threadIdx.x, wid = tid >> 5, lane = tid & 31;
    const int wm = wid & 1, wn = wid >> 1;            // 2 (m, 16 rows) x 4 (n, 32 cols)
    const int lq = lane & 3, lr = lane >> 2;
    const uint32_t aOff = (uint32_t)((((lane >> 3) & 1) * 8 + (lane & 7)) * ROWB
                                     + (lane >> 4) * 16 + (wm * 16) * ROWB);
    const uint32_t bOff = (uint32_t)(((((lane >> 4) & 1) * 8) + (lane & 7)) * ROWB
                                     + ((lane >> 3) & 1) * 16 + (wn * 32) * ROWB);

    float d[4][4];
    #pragma unroll
    for (int nt = 0; nt < 4; nt++)
        #pragma unroll
        for (int q = 0; q < 4; q++) d[nt][q] = 0.f;

    auto load_w = [&](int s, int ch) {
        uint32_t sb = smem0 + (uint32_t)(OFF_W + s * WSTGB);
        #pragma unroll
        for (int i = tid; i < 1024; i += 256) {
            int r = i >> 3, c = i & 7;
            cp_async16(sb + (uint32_t)(r * ROWB + c * 16),
                       Wg + (size_t)(bnW + r) * Kw + ch * 64 + c * 8);
        }
    };

    load_w(0, 0);
    CP_COMMIT();
    for (int ch = 0; ch < NCH; ch++) {
        if (ch + 1 < NCH) { load_w((ch + 1) & 1, ch + 1); CP_COMMIT(); CP_WAIT(1); }
        else              { CP_WAIT(0); }
        __syncthreads();
        uint32_t sA = aBase + (uint32_t)ch * CH32;
        uint32_t sB = smem0 + (uint32_t)(OFF_W + (ch & 1) * WSTGB);
        #pragma unroll
        for (int ks = 0; ks < 4; ks++) {
            uint32_t Af[4], Bf[2][4];
            ldsm_x4(Af, sA + aOff + (uint32_t)(ks * 32));
            ldsm_x4(Bf[0], sB + bOff + (uint32_t)(ks * 32));
            ldsm_x4(Bf[1], sB + bOff + (uint32_t)(16 * ROWB + ks * 32));
            #pragma unroll
            for (int nt = 0; nt < 4; nt++)
                mma_fp16(d[nt], Af, &Bf[nt >> 1][(nt & 1) * 2]);
        }
        __syncthreads();
    }

    if (PHASE == 0) {
        // bias + SiLU -> fp16 SMEM store (chunk layout)
        #pragma unroll
        for (int nt = 0; nt < 4; nt++) {
            int col = wn * 32 + nt * 8 + lq * 2;
            int gcol = bnW + col;
            float2 bb = *(const float2*)&bias[gcol];
            #pragma unroll
            for (int h = 0; h < 2; h++) {
                int row = wm * 16 + lr + h * 8;
                float x0 = d[nt][2 * h + 0] + bb.x;
                float x1 = d[nt][2 * h + 1] + bb.y;
                float s0 = x0 / (1.f + __expf(-x0));
                float s1 = x1 / (1.f + __expf(-x1));
                __half2 p = __floats2half2_rn(s0, s1);
                uint32_t addr = outBase + (uint32_t)((gcol >> 6) * CH32
                                                    + row * ROWB + (gcol & 63) * 2);
                asm volatile("st.shared.u32 [%0], %1;" :: "r"(addr), "r"(*(uint32_t*)&p));
            }
        }
        // next pass's wait+sync orders these writes before SMEM A reads
    } else {
        // bias + L2 norm + empty mask; deterministic reduce over n-warps
        float* sqp = (float*)(sm + OFF_SQP);   // [4 n-warps][32 rows]
        if (tid < 128) sqp[tid] = 0.f;
        __syncthreads();
        #pragma unroll
        for (int h = 0; h < 2; h++) {
            float s = 0.f;
            #pragma unroll
            for (int nt = 0; nt < 4; nt++) {
                int col = wn * 32 + nt * 8 + lq * 2;
                float2 bb = *(const float2*)&bias[col];
                float e0 = d[nt][2 * h + 0] + bb.x;
                float e1 = d[nt][2 * h + 1] + bb.y;
                s += e0 * e0 + e1 * e1;
            }
            s += __shfl_xor_sync(0xffffffffu, s, 1);
            s += __shfl_xor_sync(0xffffffffu, s, 2);
            if (lq == 0) sqp[wn * 32 + wm * 16 + lr + h * 8] = s;
        }
        __syncthreads();
        #pragma unroll
        for (int h = 0; h < 2; h++) {
            int rl = wm * 16 + lr + h * 8;
            float S = sqp[rl] + sqp[32 + rl] + sqp[64 + rl] + sqp[96 + rl];
            float sc = 0.f;
            if (rowcnt[bm + rl] > 0 && S > 0.f) sc = rsqrtf(S);
            #pragma unroll
            for (int nt = 0; nt < 4; nt++) {
                int col = wn * 32 + nt * 8 + lq * 2;
                float2 bb = *(const float2*)&bias[col];
                float2 v;
                v.x = (d[nt][2 * h + 0] + bb.x) * sc;
                v.y = (d[nt][2 * h + 1] + bb.y) * sc;
                *(float2*)&outF[(size_t)(bm + rl) * 128 + col] = v;
            }
        }
    }
}

// ============ fused MLP: one CTA owns a 32-row stripe through all 3 layers ============
__global__ __launch_bounds__(256, 2)
void k_mlp(const __half* __restrict__ a0g,
           const __half* __restrict__ w1, const __half* __restrict__ w2,
           const __half* __restrict__ w3,
           const float* __restrict__ b1, const float* __restrict__ b2,
           const float* __restrict__ b3,
           const int* __restrict__ rowcnt, float* __restrict__ out)
{
    extern __shared__ char sm[];
    uint32_t smem0 = smem_to_u32(sm);
    const int tid = threadIdx.x;
    const int bm = blockIdx.x * 32;
    uint32_t A0 = smem0 + OFF_A0, A1 = smem0 + OFF_A1, A2 = smem0 + OFF_A2;

    // prologue: a0 tile (2 k-chunks, 32 rows); joins pass0's first commit group
    for (int i = tid; i < 512; i += 256) {
        int ck = i >> 8, rem = i & 255, r = rem >> 3, c = rem & 7;
        cp_async16(A0 + (uint32_t)(ck * CH32 + r * ROWB + c * 16),
                   a0g + (size_t)(bm + r) * 128 + ck * 64 + c * 8);
    }

    // L1: 4 N-chunks of 128 cols, K=128 (2 chunks)
    mlp_pass<2, 0>(sm, smem0, w1, 128, 0,   A0, b1, A1, nullptr, nullptr, bm);
    mlp_pass<2, 0>(sm, smem0, w1, 128, 128, A0, b1, A1, nullptr, nullptr, bm);
    mlp_pass<2, 0>(sm, smem0, w1, 128, 256, A0, b1, A1, nullptr, nullptr, bm);
    mlp_pass<2, 0>(sm, smem0, w1, 128, 384, A0, b1, A1, nullptr, nullptr, bm);
    // L2: 2 N-chunks of 128 cols, K=512 (8 chunks)
    mlp_pass<8, 0>(sm, smem0, w2, 512, 0,   A1, b2, A2, nullptr, nullptr, bm);
    mlp_pass<8, 0>(sm, smem0, w2, 512, 128, A1, b2, A2, nullptr, nullptr, bm);
    // L3: K=256 (4 chunks) -> bias + L2norm + mask -> out
    mlp_pass<4, 1>(sm, smem0, w3, 256, 0,   A2, b3, 0,  rowcnt, out, bm);
}

// ============================ launch ============================
extern "C" void kernel_launch(void* const* d_in, const int* in_sizes, int n_in,
                              void* d_out, int out_size) {
    const float* ad    = (const float*)d_in[0];
    const void*  user  = d_in[1];
    const void*  ts    = d_in[2];
    const void*  click = d_in[3];
    const float* W1 = (const float*)d_in[4];
    const float* b1 = (const float*)d_in[5];
    const float* W2 = (const float*)d_in[6];
    const float* b2 = (const float*)d_in[7];
    const float* W3 = (const float*)d_in[8];
    const float* b3 = (const float*)d_in[9];
    float* out = (float*)d_out;

    cudaFuncSetAttribute(k_mlp, cudaFuncAttributeMaxDynamicSharedMemorySize, SMEM_TOTAL);

    __half *a0, *w1, *w2, *w3;
    int* rowcnt;
    cudaGetSymbolAddress((void**)&a0, g_a0);
    cudaGetSymbolAddress((void**)&w1, g_w1);
    cudaGetSymbolAddress((void**)&w2, g_w2);
    cudaGetSymbolAddress((void**)&w3, g_w3);
    cudaGetSymbolAddress((void**)&rowcnt, g_rowcnt);

    k_prep_wt<<<129, 512>>>(user, ts, click, W1, W2, W3);
    k_hist<<<NROWS, DIM>>>(ad, user, ts);
    k_mlp<<<NROWS / 32, 256, SMEM_TOTAL>>>(a0, w1, w2, w3, b1, b2, b3, rowcnt, out);
}

// round 12
// speedup vs baseline: 1.1270x; 1.0401x over previous
#include <cuda_runtime.h>
#include <cuda_fp16.h>
#include <cstdint>
#include <math.h>

#define NROWS 8192
#define DIM   128
#define HID1  512
#define HID2  256
#define NUSERS 512

#define ROWB   144
#define CH32   (32 * ROWB)      // one 64-col k-chunk of a 32-row activation tile: 4608 B
#define WSTGB  (128 * ROWB)     // one W k-chunk (128 n-rows): 18432 B

// dynamic smem layout for k_mlp (per CTA: 101888 B -> 2 CTAs/SM)
#define OFF_W   0                         // 2 x WSTGB = 36864
#define OFF_A0  (2 * WSTGB)               // 2 chunks  =  9216
#define OFF_A1  (OFF_A0 + 2 * CH32)       // 8 chunks  = 36864
#define OFF_A2  (OFF_A1 + 8 * CH32)       // 4 chunks  = 18432
#define OFF_SQP (OFF_A2 + 4 * CH32)       // 128 floats
#define SMEM_TOTAL (OFF_SQP + 512)        // 101888

#define PREP_SMEM (2 * NROWS * 4)         // s_idx + s_tsb = 65536

// ============ scratch ============
__device__ __align__(256) __half g_a0[NROWS * DIM];     // [8192, 128]
__device__ __align__(256) __half g_w1[HID1 * DIM];      // [512, 128]  (W1^T)
__device__ __align__(256) __half g_w2[HID2 * HID1];     // [256, 512]  (W2^T)
__device__ __align__(256) __half g_w3[DIM * HID2];      // [128, 256]  (W3^T)
__device__ int g_cnt[NUSERS], g_off[NUSERS];
__device__ int g_idx[NROWS], g_tsb[NROWS];
__device__ int g_rowcnt[NROWS];
__device__ int g_is64, g_clickbyte;

// ============================ helpers ============================
__device__ __forceinline__ uint32_t smem_to_u32(const void* p) {
    uint32_t a;
    asm("{ .reg .u64 t; cvta.to.shared.u64 t, %1; cvt.u32.u64 %0, t; }" : "=r"(a) : "l"(p));
    return a;
}
__device__ __forceinline__ void cp_async16(uint32_t smem, const void* gmem) {
    asm volatile("cp.async.cg.shared.global [%0], [%1], 16;" :: "r"(smem), "l"(gmem));
}
#define CP_COMMIT() asm volatile("cp.async.commit_group;" ::: "memory")
#define CP_WAIT(n)  asm volatile("cp.async.wait_group %0;" :: "n"(n) : "memory")

__device__ __forceinline__ void ldsm_x4(uint32_t r[4], uint32_t addr) {
    asm volatile("ldmatrix.sync.aligned.m8n8.x4.shared.b16 {%0,%1,%2,%3}, [%4];"
                 : "=r"(r[0]), "=r"(r[1]), "=r"(r[2]), "=r"(r[3]) : "r"(addr));
}
__device__ __forceinline__ void mma_fp16(float d[4], const uint32_t a[4], const uint32_t b[2]) {
    asm volatile(
        "mma.sync.aligned.m16n8k16.row.col.f32.f16.f16.f32 "
        "{%0,%1,%2,%3}, {%4,%5,%6,%7}, {%8,%9}, {%0,%1,%2,%3};"
        : "+f"(d[0]), "+f"(d[1]), "+f"(d[2]), "+f"(d[3])
        : "r"(a[0]), "r"(a[1]), "r"(a[2]), "r"(a[3]), "r"(b[0]), "r"(b[1]));
}
__device__ __forceinline__ int ld_user(const void* p, int j, int is64) {
    return is64 ? (int)((const long long*)p)[j] : ((const int*)p)[j];
}
__device__ __forceinline__ long long ld_ts(const void* p, int j, int is64) {
    return is64 ? ((const long long*)p)[j] : (long long)((const int*)p)[j];
}
__device__ __forceinline__ int ld_click(const void* p, int j, int cb) {
    return cb ? (((const unsigned char*)p)[j] != 0) : (((const int*)p)[j] != 0);
}

// ============ merged prep (block 0, shared-memory sort) + weight transpose ============
__global__ void k_prep_wt(const void* __restrict__ user, const void* __restrict__ ts,
                          const void* __restrict__ click,
                          const float* __restrict__ W1, const float* __restrict__ W2,
                          const float* __restrict__ W3) {
    if (blockIdx.x == 0) {
        extern __shared__ int s_buf[];          // s_idx[8192] | s_tsb[8192]
        int* s_idx = s_buf;
        int* s_tsb = s_buf + NROWS;
        __shared__ int cnt[NUSERS], off[NUSERS], fill[NUSERS];
        __shared__ int s_ts_or, s_click_big;
        int t = threadIdx.x;
        if (t == 0) { s_ts_or = 0; s_click_big = 0; }
        __syncthreads();
        {
            const unsigned int* tsw = (const unsigned int*)ts;
            unsigned int acc = 0;
            for (int i = t; i < 2048; i += NUSERS) acc |= tsw[2 * i + 1];
            if (acc) atomicOr(&s_ts_or, 1);
            const unsigned int* cw = (const unsigned int*)click;
            int big = 0;
            for (int i = t; i < 2048; i += NUSERS) if (cw[i] > 1u) big = 1;
            if (big) atomicOr(&s_click_big, 1);
        }
        cnt[t] = 0; fill[t] = 0;
        __syncthreads();
        int is64 = (s_ts_or == 0) ? 1 : 0;
        int cb = s_click_big ? 1 : 0;
        for (int j = t; j < NROWS; j += NUSERS)
            if (ld_click(click, j, cb)) atomicAdd(&cnt[ld_user(user, j, is64)], 1);
        __syncthreads();
        {
            int v = cnt[t];
            off[t] = v;
            __syncthreads();
            for (int o = 1; o < NUSERS; o <<= 1) {
                int x = (t >= o) ? off[t - o] : 0;
                __syncthreads();
                off[t] += x;
                __syncthreads();
            }
            off[t] -= v;
        }
        __syncthreads();
        // scatter into SHARED arrays
        for (int j = t; j < NROWS; j += NUSERS)
            if (ld_click(click, j, cb)) {
                int u = ld_user(user, j, is64);
                int pos = off[u] + atomicAdd(&fill[u], 1);
                s_idx[pos] = j;
                s_tsb[pos] = (int)ld_ts(ts, j, is64);
            }
        __syncthreads();
        // per-bucket insertion sort in SHARED memory (deterministic order by index)
        {
            int b = off[t], n = cnt[t];
            for (int i = 1; i < n; i++) {
                int kj = s_idx[b + i], kt = s_tsb[b + i];
                int p = i - 1;
                while (p >= 0 && s_idx[b + p] > kj) {
                    s_idx[b + p + 1] = s_idx[b + p];
                    s_tsb[b + p + 1] = s_tsb[b + p];
                    p--;
                }
                s_idx[b + p + 1] = kj;
                s_tsb[b + p + 1] = kt;
            }
        }
        g_off[t] = off[t];
        g_cnt[t] = cnt[t];
        __syncthreads();
        // coalesced writeback of occupied region
        int total = off[NUSERS - 1] + cnt[NUSERS - 1];
        for (int i = t; i < total; i += NUSERS) {
            g_idx[i] = s_idx[i];
            g_tsb[i] = s_tsb[i];
        }
        if (t == 0) { g_is64 = is64; g_clickbyte = cb; }
    } else {
        int stride = 128 * 512;
        int tid = (blockIdx.x - 1) * 512 + threadIdx.x;
        for (int i = tid; i < DIM * HID1; i += stride) {       // W1 [128,512] -> g_w1 [512,128]
            int k = i >> 9, n = i & 511;
            g_w1[n * DIM + k] = __float2half(W1[i]);
        }
        for (int i = tid; i < HID1 * HID2; i += stride) {      // W2 [512,256] -> g_w2 [256,512]
            int k = i >> 8, n = i & 255;
            g_w2[n * HID1 + k] = __float2half(W2[i]);
        }
        for (int i = tid; i < HID2 * DIM; i += stride) {       // W3 [256,128] -> g_w3 [128,256]
            int k = i >> 7, n = i & 127;
            g_w3[n * HID2 + k] = __float2half(W3[i]);
        }
    }
}

// ============ history: mean of clicked-earlier ad rows -> fp16 ============
__global__ void k_hist(const float* __restrict__ ad, const void* __restrict__ user,
                       const void* __restrict__ ts) {
    int i = blockIdx.x;
    int t = threadIdx.x;           // 0..127 dim
    int is64 = g_is64;
    int u = ld_user(user, i, is64);
    long long ti = ld_ts(ts, i, is64);
    int b = g_off[u], n = g_cnt[u];
    float acc = 0.f;
    int c = 0;
    for (int k = 0; k < n; k++) {
        if ((long long)g_tsb[b + k] < ti) {
            acc += ad[g_idx[b + k] * DIM + t];
            c++;
        }
    }
    float v = c ? acc / (float)c : 0.f;
    g_a0[i * DIM + t] = __float2half(v);
    if (t == 0) g_rowcnt[i] = c;
}

// ============ fused-MLP pass: 32x128 output tile over NCH k-chunks ============
// A from SMEM chunk array at aBase (32-row chunks). W streamed global -> smem db.
// PHASE 0: bias+SiLU -> fp16 into SMEM chunk layout at outBase (cols bnW..bnW+127).
// PHASE 1: bias -> L2 norm -> empty mask -> fp32 global out (cols 0..127).
template<int NCH, int PHASE>
__device__ __forceinline__ void mlp_pass(
    char* sm, uint32_t smem0,
    const __half* __restrict__ Wg, int Kw, int bnW,
    uint32_t aBase, const float* __restrict__ bias,
    uint32_t outBase,
    const int* __restrict__ rowcnt, float* __restrict__ outF, int bm)
{
    const int tid = threadIdx.x, wid = tid >> 5, lane = tid & 31;
    const int wm = wid & 1, wn = wid >> 1;            // 2 (m, 16 rows) x 4 (n, 32 cols)
    const int lq = lane & 3, lr = lane >> 2;
    const uint32_t aOff = (uint32_t)((((lane >> 3) & 1) * 8 + (lane & 7)) * ROWB
                                     + (lane >> 4) * 16 + (wm * 16) * ROWB);
    const uint32_t bOff = (uint32_t)(((((lane >> 4) & 1) * 8) + (lane & 7)) * ROWB
                                     + ((lane >> 3) & 1) * 16 + (wn * 32) * ROWB);

    float d[4][4];
    #pragma unroll
    for (int nt = 0; nt < 4; nt++)
        #pragma unroll
        for (int q = 0; q < 4; q++) d[nt][q] = 0.f;

    auto load_w = [&](int s, int ch) {
        uint32_t sb = smem0 + (uint32_t)(OFF_W + s * WSTGB);
        #pragma unroll
        for (int i = tid; i < 1024; i += 256) {
            int r = i >> 3, c = i & 7;
            cp_async16(sb + (uint32_t)(r * ROWB + c * 16),
                       Wg + (size_t)(bnW + r) * Kw + ch * 64 + c * 8);
        }
    };

    load_w(0, 0);
    CP_COMMIT();
    for (int ch = 0; ch < NCH; ch++) {
        if (ch + 1 < NCH) { load_w((ch + 1) & 1, ch + 1); CP_COMMIT(); CP_WAIT(1); }
        else              { CP_WAIT(0); }
        __syncthreads();
        uint32_t sA = aBase + (uint32_t)ch * CH32;
        uint32_t sB = smem0 + (uint32_t)(OFF_W + (ch & 1) * WSTGB);
        #pragma unroll
        for (int ks = 0; ks < 4; ks++) {
            uint32_t Af[4], Bf[2][4];
            ldsm_x4(Af, sA + aOff + (uint32_t)(ks * 32));
            ldsm_x4(Bf[0], sB + bOff + (uint32_t)(ks * 32));
            ldsm_x4(Bf[1], sB + bOff + (uint32_t)(16 * ROWB + ks * 32));
            #pragma unroll
            for (int nt = 0; nt < 4; nt++)
                mma_fp16(d[nt], Af, &Bf[nt >> 1][(nt & 1) * 2]);
        }
        __syncthreads();
    }

    if (PHASE == 0) {
        // bias + SiLU -> fp16 SMEM store (chunk layout)
        #pragma unroll
        for (int nt = 0; nt < 4; nt++) {
            int col = wn * 32 + nt * 8 + lq * 2;
            int gcol = bnW + col;
            float2 bb = *(const float2*)&bias[gcol];
            #pragma unroll
            for (int h = 0; h < 2; h++) {
                int row = wm * 16 + lr + h * 8;
                float x0 = d[nt][2 * h + 0] + bb.x;
                float x1 = d[nt][2 * h + 1] + bb.y;
                float s0 = x0 / (1.f + __expf(-x0));
                float s1 = x1 / (1.f + __expf(-x1));
                __half2 p = __floats2half2_rn(s0, s1);
                uint32_t addr = outBase + (uint32_t)((gcol >> 6) * CH32
                                                    + row * ROWB + (gcol & 63) * 2);
                asm volatile("st.shared.u32 [%0], %1;" :: "r"(addr), "r"(*(uint32_t*)&p));
            }
        }
        // next pass's wait+sync orders these writes before SMEM A reads
    } else {
        // bias + L2 norm + empty mask; deterministic reduce over n-warps
        float* sqp = (float*)(sm + OFF_SQP);   // [4 n-warps][32 rows]
        if (tid < 128) sqp[tid] = 0.f;
        __syncthreads();
        #pragma unroll
        for (int h = 0; h < 2; h++) {
            float s = 0.f;
            #pragma unroll
            for (int nt = 0; nt < 4; nt++) {
                int col = wn * 32 + nt * 8 + lq * 2;
                float2 bb = *(const float2*)&bias[col];
                float e0 = d[nt][2 * h + 0] + bb.x;
                float e1 = d[nt][2 * h + 1] + bb.y;
                s += e0 * e0 + e1 * e1;
            }
            s += __shfl_xor_sync(0xffffffffu, s, 1);
            s += __shfl_xor_sync(0xffffffffu, s, 2);
            if (lq == 0) sqp[wn * 32 + wm * 16 + lr + h * 8] = s;
        }
        __syncthreads();
        #pragma unroll
        for (int h = 0; h < 2; h++) {
            int rl = wm * 16 + lr + h * 8;
            float S = sqp[rl] + sqp[32 + rl] + sqp[64 + rl] + sqp[96 + rl];
            float sc = 0.f;
            if (rowcnt[bm + rl] > 0 && S > 0.f) sc = rsqrtf(S);
            #pragma unroll
            for (int nt = 0; nt < 4; nt++) {
                int col = wn * 32 + nt * 8 + lq * 2;
                float2 bb = *(const float2*)&bias[col];
                float2 v;
                v.x = (d[nt][2 * h + 0] + bb.x) * sc;
                v.y = (d[nt][2 * h + 1] + bb.y) * sc;
                *(float2*)&outF[(size_t)(bm + rl) * 128 + col] = v;
            }
        }
    }
}

// ============ fused MLP: one CTA owns a 32-row stripe through all 3 layers ============
__global__ __launch_bounds__(256, 2)
void k_mlp(const __half* __restrict__ a0g,
           const __half* __restrict__ w1, const __half* __restrict__ w2,
           const __half* __restrict__ w3,
           const float* __restrict__ b1, const float* __restrict__ b2,
           const float* __restrict__ b3,
           const int* __restrict__ rowcnt, float* __restrict__ out)
{
    extern __shared__ char sm[];
    uint32_t smem0 = smem_to_u32(sm);
    const int tid = threadIdx.x;
    const int bm = blockIdx.x * 32;
    uint32_t A0 = smem0 + OFF_A0, A1 = smem0 + OFF_A1, A2 = smem0 + OFF_A2;

    // prologue: a0 tile (2 k-chunks, 32 rows); joins pass0's first commit group
    for (int i = tid; i < 512; i += 256) {
        int ck = i >> 8, rem = i & 255, r = rem >> 3, c = rem & 7;
        cp_async16(A0 + (uint32_t)(ck * CH32 + r * ROWB + c * 16),
                   a0g + (size_t)(bm + r) * 128 + ck * 64 + c * 8);
    }

    // L1: 4 N-chunks of 128 cols, K=128 (2 chunks)
    mlp_pass<2, 0>(sm, smem0, w1, 128, 0,   A0, b1, A1, nullptr, nullptr, bm);
    mlp_pass<2, 0>(sm, smem0, w1, 128, 128, A0, b1, A1, nullptr, nullptr, bm);
    mlp_pass<2, 0>(sm, smem0, w1, 128, 256, A0, b1, A1, nullptr, nullptr, bm);
    mlp_pass<2, 0>(sm, smem0, w1, 128, 384, A0, b1, A1, nullptr, nullptr, bm);
    // L2: 2 N-chunks of 128 cols, K=512 (8 chunks)
    mlp_pass<8, 0>(sm, smem0, w2, 512, 0,   A1, b2, A2, nullptr, nullptr, bm);
    mlp_pass<8, 0>(sm, smem0, w2, 512, 128, A1, b2, A2, nullptr, nullptr, bm);
    // L3: K=256 (4 chunks) -> bias + L2norm + mask -> out
    mlp_pass<4, 1>(sm, smem0, w3, 256, 0,   A2, b3, 0,  rowcnt, out, bm);
}

// ============================ launch ============================
extern "C" void kernel_launch(void* const* d_in, const int* in_sizes, int n_in,
                              void* d_out, int out_size) {
    const float* ad    = (const float*)d_in[0];
    const void*  user  = d_in[1];
    const void*  ts    = d_in[2];
    const void*  click = d_in[3];
    const float* W1 = (const float*)d_in[4];
    const float* b1 = (const float*)d_in[5];
    const float* W2 = (const float*)d_in[6];
    const float* b2 = (const float*)d_in[7];
    const float* W3 = (const float*)d_in[8];
    const float* b3 = (const float*)d_in[9];
    float* out = (float*)d_out;

    cudaFuncSetAttribute(k_mlp, cudaFuncAttributeMaxDynamicSharedMemorySize, SMEM_TOTAL);
    cudaFuncSetAttribute(k_prep_wt, cudaFuncAttributeMaxDynamicSharedMemorySize, PREP_SMEM);

    __half *a0, *w1, *w2, *w3;
    int* rowcnt;
    cudaGetSymbolAddress((void**)&a0, g_a0);
    cudaGetSymbolAddress((void**)&w1, g_w1);
    cudaGetSymbolAddress((void**)&w2, g_w2);
    cudaGetSymbolAddress((void**)&w3, g_w3);
    cudaGetSymbolAddress((void**)&rowcnt, g_rowcnt);

    k_prep_wt<<<129, 512, PREP_SMEM>>>(user, ts, click, W1, W2, W3);
    k_hist<<<NROWS, DIM>>>(ad, user, ts);
    k_mlp<<<NROWS / 32, 256, SMEM_TOTAL>>>(a0, w1, w2, w3, b1, b2, b3, rowcnt, out);
}

// round 13
// speedup vs baseline: 1.2630x; 1.1207x over previous
#include <cuda_runtime.h>
#include <cuda_fp16.h>
#include <cstdint>
#include <math.h>

#define NROWS 8192
#define DIM   128
#define HID1  512
#define HID2  256
#define NUSERS 512

#define ROWB   144
#define CH32   (32 * ROWB)
#define WSTGB  (128 * ROWB)

#define OFF_W   0
#define OFF_A0  (2 * WSTGB)
#define OFF_A1  (OFF_A0 + 2 * CH32)
#define OFF_A2  (OFF_A1 + 8 * CH32)
#define OFF_SQP (OFF_A2 + 4 * CH32)
#define SMEM_TOTAL (OFF_SQP + 512)        // 101888 -> 2 CTAs/SM

// ============ scratch ============
__device__ __align__(256) __half g_a0[NROWS * DIM];
__device__ __align__(256) __half g_w1[HID1 * DIM];      // [512, 128]  (W1^T)
__device__ __align__(256) __half g_w2[HID2 * HID1];     // [256, 512]  (W2^T)
__device__ __align__(256) __half g_w3[DIM * HID2];      // [128, 256]  (W3^T)
__device__ int g_cnt[NUSERS];     // zero at module load; re-zeroed by k_mlp tail
__device__ int g_fill[NUSERS];    // ditto
__device__ int g_off[NUSERS];
__device__ int g_idx[NROWS], g_tsb[NROWS];
__device__ int g_rowcnt[NROWS];
__device__ int g_is64, g_clickbyte;

// ============================ helpers ============================
__device__ __forceinline__ uint32_t smem_to_u32(const void* p) {
    uint32_t a;
    asm("{ .reg .u64 t; cvta.to.shared.u64 t, %1; cvt.u32.u64 %0, t; }" : "=r"(a) : "l"(p));
    return a;
}
__device__ __forceinline__ void cp_async16(uint32_t smem, const void* gmem) {
    asm volatile("cp.async.cg.shared.global [%0], [%1], 16;" :: "r"(smem), "l"(gmem));
}
#define CP_COMMIT() asm volatile("cp.async.commit_group;" ::: "memory")
#define CP_WAIT(n)  asm volatile("cp.async.wait_group %0;" :: "n"(n) : "memory")

__device__ __forceinline__ void ldsm_x4(uint32_t r[4], uint32_t addr) {
    asm volatile("ldmatrix.sync.aligned.m8n8.x4.shared.b16 {%0,%1,%2,%3}, [%4];"
                 : "=r"(r[0]), "=r"(r[1]), "=r"(r[2]), "=r"(r[3]) : "r"(addr));
}
__device__ __forceinline__ void mma_fp16(float d[4], const uint32_t a[4], const uint32_t b[2]) {
    asm volatile(
        "mma.sync.aligned.m16n8k16.row.col.f32.f16.f16.f32 "
        "{%0,%1,%2,%3}, {%4,%5,%6,%7}, {%8,%9}, {%0,%1,%2,%3};"
        : "+f"(d[0]), "+f"(d[1]), "+f"(d[2]), "+f"(d[3])
        : "r"(a[0]), "r"(a[1]), "r"(a[2]), "r"(a[3]), "r"(b[0]), "r"(b[1]));
}
__device__ __forceinline__ int ld_user(const void* p, int j, int is64) {
    return is64 ? (int)((const long long*)p)[j] : ((const int*)p)[j];
}
__device__ __forceinline__ long long ld_ts(const void* p, int j, int is64) {
    return is64 ? ((const long long*)p)[j] : (long long)((const int*)p)[j];
}
__device__ __forceinline__ int ld_click(const void* p, int j, int cb) {
    return cb ? (((const unsigned char*)p)[j] != 0) : (((const int*)p)[j] != 0);
}
// local dtype detection (cheap, deterministic; any block can compute it)
__device__ __forceinline__ void detect_local(const void* ts, const void* click,
                                             int tid, int nthr, int* s_flags,
                                             int& is64, int& cb) {
    if (tid == 0) { s_flags[0] = 0; s_flags[1] = 0; }
    __syncthreads();
    const unsigned int* tsw = (const unsigned int*)ts;
    unsigned int acc = 0;
    for (int i = tid; i < 2048; i += nthr) acc |= tsw[2 * i + 1];
    if (acc) atomicOr(&s_flags[0], 1);
    const unsigned int* cw = (const unsigned int*)click;
    int big = 0;
    for (int i = tid; i < 2048; i += nthr) if (cw[i] > 1u) big = 1;
    if (big) atomicOr(&s_flags[1], 1);
    __syncthreads();
    is64 = (s_flags[0] == 0) ? 1 : 0;
    cb = s_flags[1] ? 1 : 0;
}

// ============ K1: count clicks (blocks 0..15) + weight transpose (blocks 1..128) ============
__global__ void k_count_wt(const void* __restrict__ user, const void* __restrict__ ts,
                           const void* __restrict__ click,
                           const float* __restrict__ W1, const float* __restrict__ W2,
                           const float* __restrict__ W3) {
    __shared__ int s_flags[2];
    int t = threadIdx.x;
    int blk = blockIdx.x;

    if (blk < 16) {
        int is64, cb;
        detect_local(ts, click, t, 512, s_flags, is64, cb);
        if (blk == 0 && t == 0) { g_is64 = is64; g_clickbyte = cb; }
        int j = blk * 512 + t;
        if (ld_click(click, j, cb)) atomicAdd(&g_cnt[ld_user(user, j, is64)], 1);
    }
    if (blk >= 1) {
        int stride = 128 * 512;
        int tid = (blk - 1) * 512 + t;
        for (int i = tid; i < DIM * HID1; i += stride) {       // W1 [128,512] -> [512,128]
            int k = i >> 9, n = i & 511;
            g_w1[n * DIM + k] = __float2half(W1[i]);
        }
        for (int i = tid; i < HID1 * HID2; i += stride) {      // W2 [512,256] -> [256,512]
            int k = i >> 8, n = i & 255;
            g_w2[n * HID1 + k] = __float2half(W2[i]);
        }
        for (int i = tid; i < HID2 * DIM; i += stride) {       // W3 [256,128] -> [128,256]
            int k = i >> 7, n = i & 127;
            g_w3[n * HID2 + k] = __float2half(W3[i]);
        }
    }
}

// ============ K2: scatter (each block re-derives offsets via local scan) ============
__global__ void k_scatter(const void* __restrict__ user, const void* __restrict__ ts,
                          const void* __restrict__ click) {
    __shared__ int off[NUSERS];
    int t = threadIdx.x;
    int is64 = g_is64, cb = g_clickbyte;
    // local exclusive scan of g_cnt
    int v = g_cnt[t];
    off[t] = v;
    __syncthreads();
    for (int o = 1; o < NUSERS; o <<= 1) {
        int x = (t >= o) ? off[t - o] : 0;
        __syncthreads();
        off[t] += x;
        __syncthreads();
    }
    off[t] -= v;
    if (blockIdx.x == 0) g_off[t] = off[t];
    __syncthreads();
    int j = blockIdx.x * 512 + t;
    if (ld_click(click, j, cb)) {
        int u = ld_user(user, j, is64);
        int pos = off[u] + atomicAdd(&g_fill[u], 1);
        g_idx[pos] = j;
        g_tsb[pos] = (int)ld_ts(ts, j, is64);
    }
}

// ============ K3: per-bucket sort by index, one warp per bucket (rank sort) ============
__global__ void k_sort() {
    int w = (blockIdx.x * blockDim.x + threadIdx.x) >> 5;   // bucket id
    int lane = threadIdx.x & 31;
    if (w >= NUSERS) return;
    int b = g_off[w], n = g_cnt[w];
    if (n <= 1) return;
    if (n <= 32) {
        int j = 0, tsv = 0;
        if (lane < n) { j = g_idx[b + lane]; tsv = g_tsb[b + lane]; }
        int rank = 0;
        #pragma unroll 1
        for (int l = 0; l < n; l++) {
            int oj = __shfl_sync(0xffffffffu, j, l);
            if (lane < n && l != lane && oj < j) rank++;
        }
        __syncwarp();
        if (lane < n) { g_idx[b + rank] = j; g_tsb[b + rank] = tsv; }
    } else if (lane == 0) {
        for (int i = 1; i < n; i++) {               // rare fallback
            int kj = g_idx[b + i], kt = g_tsb[b + i];
            int p = i - 1;
            while (p >= 0 && g_idx[b + p] > kj) {
                g_idx[b + p + 1] = g_idx[b + p];
                g_tsb[b + p + 1] = g_tsb[b + p];
                p--;
            }
            g_idx[b + p + 1] = kj;
            g_tsb[b + p + 1] = kt;
        }
    }
}

// ============ history: mean of clicked-earlier ad rows -> fp16 ============
__global__ void k_hist(const float* __restrict__ ad, const void* __restrict__ user,
                       const void* __restrict__ ts) {
    int i = blockIdx.x;
    int t = threadIdx.x;
    int is64 = g_is64;
    int u = ld_user(user, i, is64);
    long long ti = ld_ts(ts, i, is64);
    int b = g_off[u], n = g_cnt[u];
    float acc = 0.f;
    int c = 0;
    for (int k = 0; k < n; k++) {
        if ((long long)g_tsb[b + k] < ti) {
            acc += ad[g_idx[b + k] * DIM + t];
            c++;
        }
    }
    float v = c ? acc / (float)c : 0.f;
    g_a0[i * DIM + t] = __float2half(v);
    if (t == 0) g_rowcnt[i] = c;
}

// ============ fused-MLP pass (unchanged from passing R12 kernel) ============
template<int NCH, int PHASE>
__device__ __forceinline__ void mlp_pass(
    char* sm, uint32_t smem0,
    const __half* __restrict__ Wg, int Kw, int bnW,
    uint32_t aBase, const float* __restrict__ bias,
    uint32_t outBase,
    const int* __restrict__ rowcnt, float* __restrict__ outF, int bm)
{
    const int tid = threadIdx.x, wid = tid >> 5, lane = tid & 31;
    const int wm = wid & 1, wn = wid >> 1;
    const int lq = lane & 3, lr = lane >> 2;
    const uint32_t aOff = (uint32_t)((((lane >> 3) & 1) * 8 + (lane & 7)) * ROWB
                                     + (lane >> 4) * 16 + (wm * 16) * ROWB);
    const uint32_t bOff = (uint32_t)(((((lane >> 4) & 1) * 8) + (lane & 7)) * ROWB
                                     + ((lane >> 3) & 1) * 16 + (wn * 32) * ROWB);

    float d[4][4];
    #pragma unroll
    for (int nt = 0; nt < 4; nt++)
        #pragma unroll
        for (int q = 0; q < 4; q++) d[nt][q] = 0.f;

    auto load_w = [&](int s, int ch) {
        uint32_t sb = smem0 + (uint32_t)(OFF_W + s * WSTGB);
        #pragma unroll
        for (int i = tid; i < 1024; i += 256) {
            int r = i >> 3, c = i & 7;
            cp_async16(sb + (uint32_t)(r * ROWB + c * 16),
                       Wg + (size_t)(bnW + r) * Kw + ch * 64 + c * 8);
        }
    };

    load_w(0, 0);
    CP_COMMIT();
    for (int ch = 0; ch < NCH; ch++) {
        if (ch + 1 < NCH) { load_w((ch + 1) & 1, ch + 1); CP_COMMIT(); CP_WAIT(1); }
        else              { CP_WAIT(0); }
        __syncthreads();
        uint32_t sA = aBase + (uint32_t)ch * CH32;
        uint32_t sB = smem0 + (uint32_t)(OFF_W + (ch & 1) * WSTGB);
        #pragma unroll
        for (int ks = 0; ks < 4; ks++) {
            uint32_t Af[4], Bf[2][4];
            ldsm_x4(Af, sA + aOff + (uint32_t)(ks * 32));
            ldsm_x4(Bf[0], sB + bOff + (uint32_t)(ks * 32));
            ldsm_x4(Bf[1], sB + bOff + (uint32_t)(16 * ROWB + ks * 32));
            #pragma unroll
            for (int nt = 0; nt < 4; nt++)
                mma_fp16(d[nt], Af, &Bf[nt >> 1][(nt & 1) * 2]);
        }
        __syncthreads();
    }

    if (PHASE == 0) {
        #pragma unroll
        for (int nt = 0; nt < 4; nt++) {
            int col = wn * 32 + nt * 8 + lq * 2;
            int gcol = bnW + col;
            float2 bb = *(const float2*)&bias[gcol];
            #pragma unroll
            for (int h = 0; h < 2; h++) {
                int row = wm * 16 + lr + h * 8;
                float x0 = d[nt][2 * h + 0] + bb.x;
                float x1 = d[nt][2 * h + 1] + bb.y;
                float s0 = x0 / (1.f + __expf(-x0));
                float s1 = x1 / (1.f + __expf(-x1));
                __half2 p = __floats2half2_rn(s0, s1);
                uint32_t addr = outBase + (uint32_t)((gcol >> 6) * CH32
                                                    + row * ROWB + (gcol & 63) * 2);
                asm volatile("st.shared.u32 [%0], %1;" :: "r"(addr), "r"(*(uint32_t*)&p));
            }
        }
    } else {
        float* sqp = (float*)(sm + OFF_SQP);
        if (tid < 128) sqp[tid] = 0.f;
        __syncthreads();
        #pragma unroll
        for (int h = 0; h < 2; h++) {
            float s = 0.f;
            #pragma unroll
            for (int nt = 0; nt < 4; nt++) {
                int col = wn * 32 + nt * 8 + lq * 2;
                float2 bb = *(const float2*)&bias[col];
                float e0 = d[nt][2 * h + 0] + bb.x;
                float e1 = d[nt][2 * h + 1] + bb.y;
                s += e0 * e0 + e1 * e1;
            }
            s += __shfl_xor_sync(0xffffffffu, s, 1);
            s += __shfl_xor_sync(0xffffffffu, s, 2);
            if (lq == 0) sqp[wn * 32 + wm * 16 + lr + h * 8] = s;
        }
        __syncthreads();
        #pragma unroll
        for (int h = 0; h < 2; h++) {
            int rl = wm * 16 + lr + h * 8;
            float S = sqp[rl] + sqp[32 + rl] + sqp[64 + rl] + sqp[96 + rl];
            float sc = 0.f;
            if (rowcnt[bm + rl] > 0 && S > 0.f) sc = rsqrtf(S);
            #pragma unroll
            for (int nt = 0; nt < 4; nt++) {
                int col = wn * 32 + nt * 8 + lq * 2;
                float2 bb = *(const float2*)&bias[col];
                float2 v;
                v.x = (d[nt][2 * h + 0] + bb.x) * sc;
                v.y = (d[nt][2 * h + 1] + bb.y) * sc;
                *(float2*)&outF[(size_t)(bm + rl) * 128 + col] = v;
            }
        }
    }
}

// ============ fused MLP: one CTA per 32-row stripe; tail re-zeroes counters ============
__global__ __launch_bounds__(256, 2)
void k_mlp(const __half* __restrict__ a0g,
           const __half* __restrict__ w1, const __half* __restrict__ w2,
           const __half* __restrict__ w3,
           const float* __restrict__ b1, const float* __restrict__ b2,
           const float* __restrict__ b3,
           const int* __restrict__ rowcnt, float* __restrict__ out)
{
    extern __shared__ char sm[];
    uint32_t smem0 = smem_to_u32(sm);
    const int tid = threadIdx.x;
    const int bm = blockIdx.x * 32;
    uint32_t A0 = smem0 + OFF_A0, A1 = smem0 + OFF_A1, A2 = smem0 + OFF_A2;

    for (int i = tid; i < 512; i += 256) {
        int ck = i >> 8, rem = i & 255, r = rem >> 3, c = rem & 7;
        cp_async16(A0 + (uint32_t)(ck * CH32 + r * ROWB + c * 16),
                   a0g + (size_t)(bm + r) * 128 + ck * 64 + c * 8);
    }

    mlp_pass<2, 0>(sm, smem0, w1, 128, 0,   A0, b1, A1, nullptr, nullptr, bm);
    mlp_pass<2, 0>(sm, smem0, w1, 128, 128, A0, b1, A1, nullptr, nullptr, bm);
    mlp_pass<2, 0>(sm, smem0, w1, 128, 256, A0, b1, A1, nullptr, nullptr, bm);
    mlp_pass<2, 0>(sm, smem0, w1, 128, 384, A0, b1, A1, nullptr, nullptr, bm);
    mlp_pass<8, 0>(sm, smem0, w2, 512, 0,   A1, b2, A2, nullptr, nullptr, bm);
    mlp_pass<8, 0>(sm, smem0, w2, 512, 128, A1, b2, A2, nullptr, nullptr, bm);
    mlp_pass<4, 1>(sm, smem0, w3, 256, 0,   A2, b3, 0,  rowcnt, out, bm);

    // reset counters for the next (graph-replayed) call — keeps every call's
    // entry state identical (module-load zeros cover the very first call)
    if (blockIdx.x == 0 && tid < 256) {
        g_cnt[tid] = 0;  g_cnt[tid + 256] = 0;
        g_fill[tid] = 0; g_fill[tid + 256] = 0;
    }
}

// ============================ launch ============================
extern "C" void kernel_launch(void* const* d_in, const int* in_sizes, int n_in,
                              void* d_out, int out_size) {
    const float* ad    = (const float*)d_in[0];
    const void*  user  = d_in[1];
    const void*  ts    = d_in[2];
    const void*  click = d_in[3];
    const float* W1 = (const float*)d_in[4];
    const float* b1 = (const float*)d_in[5];
    const float* W2 = (const float*)d_in[6];
    const float* b2 = (const float*)d_in[7];
    const float* W3 = (const float*)d_in[8];
    const float* b3 = (const float*)d_in[9];
    float* out = (float*)d_out;

    cudaFuncSetAttribute(k_mlp, cudaFuncAttributeMaxDynamicSharedMemorySize, SMEM_TOTAL);

    __half *a0, *w1, *w2, *w3;
    int* rowcnt;
    cudaGetSymbolAddress((void**)&a0, g_a0);
    cudaGetSymbolAddress((void**)&w1, g_w1);
    cudaGetSymbolAddress((void**)&w2, g_w2);
    cudaGetSymbolAddress((void**)&w3, g_w3);
    cudaGetSymbolAddress((void**)&rowcnt, g_rowcnt);

    k_count_wt<<<129, 512>>>(user, ts, click, W1, W2, W3);
    k_scatter<<<16, 512>>>(user, ts, click);
    k_sort<<<16, 1024>>>();
    k_hist<<<NROWS, DIM>>>(ad, user, ts);
    k_mlp<<<NROWS / 32, 256, SMEM_TOTAL>>>(a0, w1, w2, w3, b1, b2, b3, rowcnt, out);
}